// round 14
// baseline (speedup 1.0000x reference)
#include <cuda_runtime.h>
#include <cstdint>

#define BATCH 4
#define SEQ   1024
#define EMB   768
#define HEADS 12
#define HDIM  64
#define BH    (BATCH*HEADS)    // 48
#define NSPL  16               // scan row-chunk replicas
#define SCAN_BLKS (BH * NSPL)  // 768

#define RS_ONE   (BH * HEADS * EMB)      // 442368 floats per replica
#define G_ELEMS  (BATCH * EMB)
#define G_OFF    (NSPL * RS_ONE)

// [0, NSPL*RS_ONE) = RS replicas (fully overwritten by scan every call)
// [G_OFF, +G_ELEMS) = G (zeroed by scan block 0, atomic-reduced by kgemm)
__device__ float g_Acc[NSPL * RS_ONE + G_ELEMS];

// Precomputed geometry, h-indexed.  A(h,c) = ceil((1024h - c)/12); segment of
// (h,c) is rows [A(h,c), A(h+1,c)).  aMin/cut1 = min/max_c A(h,c);
// cut2/bMax = min/max_c A(h+1,c).  add0 bit c: A(h,c)==aMin; add2 bit c:
// A(h+1,c)==bMax.
__constant__ short c_aMin[12] = {0, 85,170,256,341,426,512,597,682,768,853,938};
__constant__ short c_cut1[12] = {0, 86,171,256,342,427,512,598,683,768,854,939};
__constant__ short c_cut2[12] = {85,170,256,341,426,512,597,682,768,853,938,1024};
__constant__ short c_bMax[12] = {86,171,256,342,427,512,598,683,768,854,939,1024};
__constant__ unsigned c_add0[12] = {0xFFF,0xFF0,0xF00,0xFFF,0xFF0,0xF00,
                                    0xFFF,0xFF0,0xF00,0xFFF,0xFF0,0xF00};
__constant__ unsigned c_add2[12] = {0x00F,0x0FF,0xFFF,0x00F,0x0FF,0xFFF,
                                    0x00F,0x0FF,0xFFF,0x00F,0x0FF,0xFFF};

// ---------------------------------------------------------------------------
// K1: scan.  grid = 768: x = bh*NSPL + rc.  block = 192 thr = one full
// 768-float row as float4.  ~5 rows per block; P0/P1/P2 sub-loops around the
// uniform cuts; 12 direct STG.128 into replica rc.  No atomics, no smem.
// ---------------------------------------------------------------------------
__global__ void __launch_bounds__(192) scan_kernel(const float* __restrict__ value)
{
    const int x  = blockIdx.x;
    const int rc = x % NSPL;
    const int bh = x / NSPL;
    const int b = bh / HEADS, h = bh % HEADS;
    const int tid = threadIdx.x;

    if (x == 0) {    // zero G (768 float4)
        float4* Gz = (float4*)(g_Acc + G_OFF);
        #pragma unroll
        for (int i = 0; i < 4; i++)
            Gz[tid + 192 * i] = make_float4(0.f, 0.f, 0.f, 0.f);
    }

    const int aMin = c_aMin[h], cut1 = c_cut1[h];
    const int cut2 = c_cut2[h], bMax = c_bMax[h];
    const unsigned m0 = c_add0[h], m2 = c_add2[h];

    const int L  = bMax - aMin;
    const int lo = aMin + (L * rc)      / NSPL;
    const int hi = aMin + (L * (rc + 1)) / NSPL;

    const float4* vp = (const float4*)(value + (size_t)b * SEQ * EMB) + tid;

    float4 P0 = make_float4(0.f,0.f,0.f,0.f), P1 = P0, P2 = P0;
    {   const int e = min(hi, cut1);
        for (int s = lo; s < e; s++) {
            float4 v = vp[(size_t)s * 192];
            P0.x += v.x; P0.y += v.y; P0.z += v.z; P0.w += v.w;
        }
    }
    {   const int st = max(lo, cut1), e = min(hi, cut2);
        #pragma unroll 4
        for (int s = st; s < e; s++) {
            float4 v = vp[(size_t)s * 192];
            P1.x += v.x; P1.y += v.y; P1.z += v.z; P1.w += v.w;
        }
    }
    {   const int st = max(lo, cut2);
        for (int s = st; s < hi; s++) {
            float4 v = vp[(size_t)s * 192];
            P2.x += v.x; P2.y += v.y; P2.z += v.z; P2.w += v.w;
        }
    }

    float4* R = (float4*)(g_Acc + (size_t)rc * RS_ONE) + (size_t)bh * HEADS * 192 + tid;
    #pragma unroll
    for (int c = 0; c < 12; c++) {
        float4 r = P1;
        if ((m0 >> c) & 1) { r.x+=P0.x; r.y+=P0.y; r.z+=P0.z; r.w+=P0.w; }
        if ((m2 >> c) & 1) { r.x+=P2.x; r.y+=P2.y; r.z+=P2.z; r.w+=P2.w; }
        R[c * 192] = r;
    }
}

// ---------------------------------------------------------------------------
// K2: K-split GEMM (PDL consumer).  grid = 144, 192 threads.
// Loads Wv tile BEFORE the grid-dependency sync (independent of scan), then
// syncs and loads the RS replica sum.
// ---------------------------------------------------------------------------
__global__ void __launch_bounds__(192) kgemm_kernel(const float* __restrict__ Wv)
{
    const int c  = blockIdx.x / 12;
    const int jt = blockIdx.x % 12;
    const int tid = threadIdx.x;

    __shared__ float As_t[64][52];   // [k][bh]
    __shared__ float Ws_t[64][68];   // [k][d]

    // Ws_t[k][d] = Wv[64c+d][64jt + k]  — independent of scan output
    for (int f = tid; f < 1024; f += 192) {
        int d = f >> 4, kq = f & 15;
        float4 v = *(const float4*)(Wv + (size_t)(64 * c + d) * EMB + jt * 64 + kq * 4);
        Ws_t[4*kq+0][d] = v.x; Ws_t[4*kq+1][d] = v.y;
        Ws_t[4*kq+2][d] = v.z; Ws_t[4*kq+3][d] = v.w;
    }

    cudaGridDependencySynchronize();     // wait for scan's RS + G-zero

    // As_t[k][bh] = sum over replicas of RS[bh][c][64jt + k]
    for (int f = tid; f < 768; f += 192) {
        int bh = f >> 4, kq = f & 15;
        const size_t off = ((size_t)bh * HEADS + c) * 192 + jt * 16 + kq;
        float4 v = ((const float4*)g_Acc)[off];
        #pragma unroll
        for (int rc = 1; rc < NSPL; rc++) {
            float4 u = ((const float4*)(g_Acc + (size_t)rc * RS_ONE))[off];
            v.x += u.x; v.y += u.y; v.z += u.z; v.w += u.w;
        }
        As_t[4*kq+0][bh] = v.x; As_t[4*kq+1][bh] = v.y;
        As_t[4*kq+2][bh] = v.z; As_t[4*kq+3][bh] = v.w;
    }
    __syncthreads();

    const int tx = tid & 15;     // 4 d's
    const int ty = tid >> 4;     // 0..11 -> 4 bh's

    float acc[4][4] = {};
    #pragma unroll 8
    for (int k = 0; k < 64; k++) {
        float4 a4 = *(const float4*)&As_t[k][ty * 4];
        float4 b4 = *(const float4*)&Ws_t[k][tx * 4];
        const float a[4]  = {a4.x, a4.y, a4.z, a4.w};
        const float bb[4] = {b4.x, b4.y, b4.z, b4.w};
        #pragma unroll
        for (int u = 0; u < 4; u++)
            #pragma unroll
            for (int v = 0; v < 4; v++)
                acc[u][v] = fmaf(a[u], bb[v], acc[u][v]);
    }

    #pragma unroll
    for (int u = 0; u < 4; u++) {
        int bh = ty * 4 + u;
        int b = bh / HEADS, hh = bh % HEADS;
        float* gp = g_Acc + G_OFF + b * EMB + hh * HDIM + tx * 4;
        #pragma unroll
        for (int v = 0; v < 4; v++)
            atomicAdd(gp + v, acc[u][v]);
    }
}

// ---------------------------------------------------------------------------
// K3: broadcast (PDL consumer).  1024 blocks x 192 threads, 4 rows per block.
// ---------------------------------------------------------------------------
__global__ void __launch_bounds__(192) broadcast_kernel(float* __restrict__ out)
{
    cudaGridDependencySynchronize();     // wait for kgemm's G

    const int row0 = blockIdx.x * 4;           // 4 | 1024 -> single b per block
    const int b = row0 >> 10;
    const int c4 = threadIdx.x;

    const float4 v = ((const float4*)(g_Acc + G_OFF + b * EMB))[c4];
    float4* o = (float4*)(out + (size_t)row0 * EMB) + c4;
    #pragma unroll
    for (int i = 0; i < 4; i++)
        o[(size_t)i * 192] = v;
}

// ---------------------------------------------------------------------------
extern "C" void kernel_launch(void* const* d_in, const int* in_sizes, int n_in,
                              void* d_out, int out_size)
{
    // metadata order: key, query, value, Wk, Wq, Wv
    const float* value = (const float*)d_in[2];
    const float* Wv    = (const float*)d_in[5];
    float* out = (float*)d_out;

    scan_kernel<<<SCAN_BLKS, 192>>>(value);

    cudaLaunchAttribute attr[1];
    attr[0].id = cudaLaunchAttributeProgrammaticStreamSerialization;
    attr[0].val.programmaticStreamSerializationAllowed = 1;

    {
        cudaLaunchConfig_t cfg = {};
        cfg.gridDim = dim3(144, 1, 1);
        cfg.blockDim = dim3(192, 1, 1);
        cfg.dynamicSmemBytes = 0;
        cfg.stream = 0;
        cfg.attrs = attr;
        cfg.numAttrs = 1;
        cudaLaunchKernelEx(&cfg, kgemm_kernel, Wv);
    }
    {
        cudaLaunchConfig_t cfg = {};
        cfg.gridDim = dim3(1024, 1, 1);
        cfg.blockDim = dim3(192, 1, 1);
        cfg.dynamicSmemBytes = 0;
        cfg.stream = 0;
        cfg.attrs = attr;
        cfg.numAttrs = 1;
        cudaLaunchKernelEx(&cfg, broadcast_kernel, out);
    }
}

// round 15
// speedup vs baseline: 1.6387x; 1.6387x over previous
#include <cuda_runtime.h>
#include <cstdint>

#define BATCH 4
#define SEQ   1024
#define EMB   768
#define HEADS 12
#define HDIM  64

#define SLOTS 296                     // per b: 12 long ranges * 24 splits + 8 singles
#define PP_FLOATS (BATCH * SLOTS * EMB)      // 909312
#define W_OFF  PP_FLOATS
#define WARR4  12288                  // one 64x768 W-array in float4 units
#define G2_OFF (W_OFF + 5 * 4 * WARR4)       // after W0,W4,W8,L4,L8

__device__ float g_Acc[G2_OFF + BATCH * EMB];

// Geometry: A(h,c) = ceil((1024h - c)/12).
// aMin(h) = A(h,11), cut1(h) = A(h,0).  R2(h) = [cut1(h), aMin(h+1)).
__constant__ short c_aMin[13]  = {0,85,170,256,341,426,512,597,682,768,853,938,1024};
__constant__ short c_cut1[12]  = {0,86,171,256,342,427,512,598,683,768,854,939};
__constant__ short c_single[8] = {85,170,341,426,597,682,853,938};   // aMin(h), h=1,2,4,5,7,8,10,11
__constant__ signed char c_r1slot[13] = {-1,0,1,-1,2,3,-1,4,5,-1,6,7,-1};

__device__ __forceinline__ float4 f4add(float4 a, float4 b)
{ return make_float4(a.x+b.x, a.y+b.y, a.z+b.z, a.w+b.w); }

// ---------------------------------------------------------------------------
// K1: prep.  grid = 1248 x 192.
//  blocks [0,64):    W-array build.  block = d; thread = j4.
//  blocks [64,1248): range-partial scan.  (b, slot) single-writer, no atomics.
// ---------------------------------------------------------------------------
__global__ void __launch_bounds__(192) prep_kernel(
    const float* __restrict__ value, const float* __restrict__ Wv)
{
    const int x = blockIdx.x, tid = threadIdx.x;

    if (x < 64) {
        const int d = x;
        const float4* wr = (const float4*)Wv;
        float4 u[12];
        #pragma unroll
        for (int c = 0; c < 12; c++)
            u[c] = wr[(size_t)(64 * c + d) * 192 + tid];
        float4 U2 = f4add(f4add(u[8], u[9]),  f4add(u[10], u[11]));
        float4 U1 = f4add(f4add(u[4], u[5]),  f4add(u[6],  u[7]));
        float4 U0 = f4add(f4add(u[0], u[1]),  f4add(u[2],  u[3]));
        float4 W8v = U2;
        float4 W4v = f4add(U1, U2);
        float4 W0v = f4add(U0, W4v);
        float4 L4v = U0;
        float4 L8v = f4add(U0, U1);
        float4* W = (float4*)(g_Acc + W_OFF);
        const size_t o = (size_t)d * 192 + tid;
        W[0 * WARR4 + o] = W0v;
        W[1 * WARR4 + o] = W4v;
        W[2 * WARR4 + o] = W8v;
        W[3 * WARR4 + o] = L4v;
        W[4 * WARR4 + o] = L8v;
    } else {
        const int r  = x - 64;
        const int b  = r / SLOTS;
        const int rr = r % SLOTS;
        int lo, hi;
        if (rr < 288) {
            const int h = rr / 24, sp = rr % 24;
            const int c1 = c_cut1[h];
            const int L  = c_aMin[h + 1] - c1;     // 84 or 85
            lo = c1 + (L * sp) / 24;
            hi = c1 + (L * (sp + 1)) / 24;
        } else {
            lo = c_single[rr - 288];
            hi = lo + 1;
        }
        const float4* vp = (const float4*)(value + (size_t)b * SEQ * EMB) + tid;
        float4 acc = make_float4(0.f, 0.f, 0.f, 0.f);
        for (int s = lo; s < hi; s++)
            acc = f4add(acc, vp[(size_t)s * 192]);
        ((float4*)g_Acc)[(size_t)(b * SLOTS + rr) * 192 + tid] = acc;
    }
}

// ---------------------------------------------------------------------------
// K2: contract.  grid = 96 = (b*12+h)*2 + dhalf, 256 threads.
// smem R1/R2/R3 (R2 = sum of 24 splits); per-case coefficient arrays:
//   h%3=0: G = W0*R2 + L4*R3        (R1 zeroed, coeffA dummy)
//   h%3=1: G = W4*R1 + W0*R2 + L8*R3
//   h%3=2: G = W8*R1 + W0*R2        (R3 zeroed, coeffC dummy)
// warp w handles d = dhalf*32 + w*4 + {0..3}; lanes split j; single STG per G.
// ---------------------------------------------------------------------------
__global__ void __launch_bounds__(256) contract_kernel()
{
    const int x  = blockIdx.x;
    const int b  = x / 24;
    const int h  = (x % 24) >> 1;
    const int dh = x & 1;
    const int tid = threadIdx.x;

    __shared__ float4 R1s[192], R2s[192], R3s[192];

    if (tid < 192) {
        const float4* Pp = (const float4*)g_Acc + (size_t)b * SLOTS * 192;
        float4 a = make_float4(0.f, 0.f, 0.f, 0.f);
        #pragma unroll
        for (int sp = 0; sp < 24; sp++)
            a = f4add(a, Pp[(size_t)(h * 24 + sp) * 192 + tid]);
        R2s[tid] = a;
        const int s1 = c_r1slot[h];
        R1s[tid] = (s1 >= 0) ? Pp[(size_t)(288 + s1) * 192 + tid]
                             : make_float4(0.f, 0.f, 0.f, 0.f);
        const int s3 = c_r1slot[h + 1];
        R3s[tid] = (s3 >= 0) ? Pp[(size_t)(288 + s3) * 192 + tid]
                             : make_float4(0.f, 0.f, 0.f, 0.f);
    }
    __syncthreads();

    const int hm = h % 3;
    const float4* Wbase = (const float4*)(g_Acc + W_OFF);
    const float4* WA = Wbase + (hm == 1 ? 1 : hm == 2 ? 2 : 0) * WARR4;  // R1 coeff
    const float4* WB = Wbase;                                            // W0
    const float4* WC = Wbase + (hm == 0 ? 3 : hm == 1 ? 4 : 0) * WARR4;  // R3 coeff

    const int w = tid >> 5, l = tid & 31;
    #pragma unroll
    for (int du = 0; du < 4; du++) {
        const int d = dh * 32 + w * 4 + du;
        float s = 0.f;
        #pragma unroll
        for (int i = 0; i < 6; i++) {
            const int idx = l + i * 32;
            float4 a4 = WA[(size_t)d * 192 + idx];
            float4 b4 = WB[(size_t)d * 192 + idx];
            float4 c4 = WC[(size_t)d * 192 + idx];
            float4 r1 = R1s[idx], r2 = R2s[idx], r3 = R3s[idx];
            s += a4.x*r1.x + a4.y*r1.y + a4.z*r1.z + a4.w*r1.w
               + b4.x*r2.x + b4.y*r2.y + b4.z*r2.z + b4.w*r2.w
               + c4.x*r3.x + c4.y*r3.y + c4.z*r3.z + c4.w*r3.w;
        }
        #pragma unroll
        for (int o = 16; o; o >>= 1) s += __shfl_down_sync(~0u, s, o);
        if (l == 0)
            g_Acc[G2_OFF + b * EMB + h * HDIM + d] = s;
    }
}

// ---------------------------------------------------------------------------
// K3: out[b, q, :] = G[b, :].  1024 blocks x 192 threads, 4 rows per block.
// ---------------------------------------------------------------------------
__global__ void __launch_bounds__(192) broadcast_kernel(float* __restrict__ out)
{
    const int row0 = blockIdx.x * 4;           // 4 | 1024 -> single b per block
    const int b = row0 >> 10;
    const int c4 = threadIdx.x;

    const float4 v = ((const float4*)(g_Acc + G2_OFF + b * EMB))[c4];
    float4* o = (float4*)(out + (size_t)row0 * EMB) + c4;
    #pragma unroll
    for (int i = 0; i < 4; i++)
        o[(size_t)i * 192] = v;
}

// ---------------------------------------------------------------------------
extern "C" void kernel_launch(void* const* d_in, const int* in_sizes, int n_in,
                              void* d_out, int out_size)
{
    // metadata order: key, query, value, Wk, Wq, Wv
    const float* value = (const float*)d_in[2];
    const float* Wv    = (const float*)d_in[5];
    float* out = (float*)d_out;

    prep_kernel<<<64 + BATCH * SLOTS, 192>>>(value, Wv);
    contract_kernel<<<96, 256>>>();
    broadcast_kernel<<<1024, 192>>>(out);
}

// round 16
// speedup vs baseline: 1.8200x; 1.1106x over previous
#include <cuda_runtime.h>
#include <cstdint>

#define BATCH 4
#define SEQ   1024
#define EMB   768
#define HEADS 12
#define HDIM  64

#define NSP   12                      // splits per long range
#define SLOTS (12*NSP + 8)            // per b: 144 long splits + 8 singles = 152
#define PP_FLOATS (BATCH * SLOTS * EMB)
#define W_OFF  PP_FLOATS
#define WARR4  12288                  // one 64x768 W-array in float4 units
// g_Acc: [0, PP) = range partials; [W_OFF, +5*WARR4*4) = W0,W4,W8,L4,L8

__device__ float g_Acc[W_OFF + 5 * 4 * WARR4];

// Geometry: A(h,c) = ceil((1024h - c)/12).
// aMin(h) = A(h,11), cut1(h) = A(h,0).  R2(h) = [cut1(h), aMin(h+1)).
__constant__ short c_aMin[13]  = {0,85,170,256,341,426,512,597,682,768,853,938,1024};
__constant__ short c_cut1[12]  = {0,86,171,256,342,427,512,598,683,768,854,939};
__constant__ short c_single[8] = {85,170,341,426,597,682,853,938};   // aMin(h), h=1,2,4,5,7,8,10,11
__constant__ signed char c_r1slot[13] = {-1,0,1,-1,2,3,-1,4,5,-1,6,7,-1};

__device__ __forceinline__ float4 f4add(float4 a, float4 b)
{ return make_float4(a.x+b.x, a.y+b.y, a.z+b.z, a.w+b.w); }

// ---------------------------------------------------------------------------
// K1: prep.  grid = 64 + 4*SLOTS = 672, block = 192.
//  blocks [0,64):  W-array build (block = d, thread = j4).
//  rest:           range-partial scan, ~7 rows/slot, 2 accumulators,
//                  single-writer stores, no atomics.
// ---------------------------------------------------------------------------
__global__ void __launch_bounds__(192) prep_kernel(
    const float* __restrict__ value, const float* __restrict__ Wv)
{
    const int x = blockIdx.x, tid = threadIdx.x;

    if (x < 64) {
        const int d = x;
        const float4* wr = (const float4*)Wv;
        float4 u[12];
        #pragma unroll
        for (int c = 0; c < 12; c++)
            u[c] = wr[(size_t)(64 * c + d) * 192 + tid];
        float4 U2 = f4add(f4add(u[8], u[9]),  f4add(u[10], u[11]));
        float4 U1 = f4add(f4add(u[4], u[5]),  f4add(u[6],  u[7]));
        float4 U0 = f4add(f4add(u[0], u[1]),  f4add(u[2],  u[3]));
        float4 W8v = U2;
        float4 W4v = f4add(U1, U2);
        float4 W0v = f4add(U0, W4v);
        float4 L4v = U0;
        float4 L8v = f4add(U0, U1);
        float4* W = (float4*)(g_Acc + W_OFF);
        const size_t o = (size_t)d * 192 + tid;
        W[0 * WARR4 + o] = W0v;
        W[1 * WARR4 + o] = W4v;
        W[2 * WARR4 + o] = W8v;
        W[3 * WARR4 + o] = L4v;
        W[4 * WARR4 + o] = L8v;
    } else {
        const int r  = x - 64;
        const int b  = r / SLOTS;
        const int rr = r % SLOTS;
        int lo, hi;
        if (rr < 12 * NSP) {
            const int h = rr / NSP, sp = rr % NSP;
            const int c1 = c_cut1[h];
            const int L  = c_aMin[h + 1] - c1;     // 84 or 85
            lo = c1 + (L * sp) / NSP;
            hi = c1 + (L * (sp + 1)) / NSP;
        } else {
            lo = c_single[rr - 12 * NSP];
            hi = lo + 1;
        }
        const float4* vp = (const float4*)(value + (size_t)b * SEQ * EMB) + tid;
        float4 a0 = make_float4(0.f, 0.f, 0.f, 0.f), a1 = a0;
        int s = lo;
        for (; s + 1 < hi; s += 2) {
            a0 = f4add(a0, vp[(size_t)s * 192]);
            a1 = f4add(a1, vp[(size_t)(s + 1) * 192]);
        }
        if (s < hi) a0 = f4add(a0, vp[(size_t)s * 192]);
        ((float4*)g_Acc)[(size_t)(b * SLOTS + rr) * 192 + tid] = f4add(a0, a1);
    }
}

// ---------------------------------------------------------------------------
// K2: contract + broadcast (fused).  grid = 96 = (b*12+h)*2 + dhalf, 256 thr.
// Build R1/R2/R3 in smem; per-case coefficients:
//   h%3=0: G = W0*R2 + L4*R3
//   h%3=1: G = W4*R1 + W0*R2 + L8*R3
//   h%3=2: G = W8*R1 + W0*R2
// warp w computes d = dh*32 + w*4 + {0..3} -> Gs[32]; then the block
// broadcasts its 32-float slice to out[b, q, h*64+dh*32..+32) for all q.
// ---------------------------------------------------------------------------
__global__ void __launch_bounds__(256) contract_kernel(float* __restrict__ out)
{
    const int x  = blockIdx.x;
    const int b  = x / 24;
    const int h  = (x % 24) >> 1;
    const int dh = x & 1;
    const int tid = threadIdx.x;

    __shared__ float4 R1s[192], R2s[192], R3s[192];
    __shared__ float  Gs[32];

    if (tid < 192) {
        const float4* Pp = (const float4*)g_Acc + (size_t)b * SLOTS * 192;
        float4 a = make_float4(0.f, 0.f, 0.f, 0.f);
        #pragma unroll
        for (int sp = 0; sp < NSP; sp++)
            a = f4add(a, Pp[(size_t)(h * NSP + sp) * 192 + tid]);
        R2s[tid] = a;
        const int s1 = c_r1slot[h];
        R1s[tid] = (s1 >= 0) ? Pp[(size_t)(12 * NSP + s1) * 192 + tid]
                             : make_float4(0.f, 0.f, 0.f, 0.f);
        const int s3 = c_r1slot[h + 1];
        R3s[tid] = (s3 >= 0) ? Pp[(size_t)(12 * NSP + s3) * 192 + tid]
                             : make_float4(0.f, 0.f, 0.f, 0.f);
    }
    __syncthreads();

    const int hm = h % 3;
    const float4* Wbase = (const float4*)(g_Acc + W_OFF);
    const float4* WA = Wbase + (hm == 1 ? 1 : hm == 2 ? 2 : 0) * WARR4;  // R1 coeff
    const float4* WB = Wbase;                                            // W0
    const float4* WC = Wbase + (hm == 0 ? 3 : hm == 1 ? 4 : 0) * WARR4;  // R3 coeff

    const int w = tid >> 5, l = tid & 31;
    #pragma unroll
    for (int du = 0; du < 4; du++) {
        const int d = dh * 32 + w * 4 + du;
        float s = 0.f;
        #pragma unroll
        for (int i = 0; i < 6; i++) {
            const int idx = l + i * 32;
            float4 a4 = WA[(size_t)d * 192 + idx];
            float4 b4 = WB[(size_t)d * 192 + idx];
            float4 c4 = WC[(size_t)d * 192 + idx];
            float4 r1 = R1s[idx], r2 = R2s[idx], r3 = R3s[idx];
            s += a4.x*r1.x + a4.y*r1.y + a4.z*r1.z + a4.w*r1.w
               + b4.x*r2.x + b4.y*r2.y + b4.z*r2.z + b4.w*r2.w
               + c4.x*r3.x + c4.y*r3.y + c4.z*r3.z + c4.w*r3.w;
        }
        #pragma unroll
        for (int o = 16; o; o >>= 1) s += __shfl_down_sync(~0u, s, o);
        if (l == 0) Gs[w * 4 + du] = s;
    }
    __syncthreads();

    // broadcast: out[b, q, h*64 + dh*32 + 0..32) = Gs for all q
    const float4 g0 = ((const float4*)Gs)[tid & 7];
    float* obase = out + (size_t)b * SEQ * EMB + h * HDIM + dh * 32;
    const int r0 = tid >> 3;                   // 0..31
    #pragma unroll
    for (int it = 0; it < 32; it++) {
        const int row = it * 32 + r0;
        ((float4*)(obase + (size_t)row * EMB))[tid & 7] = g0;
    }
}

// ---------------------------------------------------------------------------
extern "C" void kernel_launch(void* const* d_in, const int* in_sizes, int n_in,
                              void* d_out, int out_size)
{
    // metadata order: key, query, value, Wk, Wq, Wv
    const float* value = (const float*)d_in[2];
    const float* Wv    = (const float*)d_in[5];
    float* out = (float*)d_out;

    prep_kernel<<<64 + BATCH * SLOTS, 192>>>(value, Wv);
    contract_kernel<<<96, 256>>>(out);
}

// round 17
// speedup vs baseline: 1.8728x; 1.0290x over previous
#include <cuda_runtime.h>
#include <cstdint>

#define BATCH 4
#define SEQ   1024
#define EMB   768
#define HEADS 12
#define HDIM  64

#define NSP   12                      // splits per long range
#define SLOTS (12*NSP + 8)            // per b: 144 long splits + 8 singles = 152
#define PP_FLOATS (BATCH * SLOTS * EMB)
#define W_OFF  PP_FLOATS
#define WARR4  12288                  // one 64x768 W-array in float4 units
// g_Acc: [0, PP) = range partials; [W_OFF, +5*WARR4*4) = W0,W4,W8,L4,L8

__device__ float g_Acc[W_OFF + 5 * 4 * WARR4];

// Geometry: A(h,c) = ceil((1024h - c)/12).
// aMin(h) = A(h,11), cut1(h) = A(h,0).  R2(h) = [cut1(h), aMin(h+1)).
__constant__ short c_aMin[13]  = {0,85,170,256,341,426,512,597,682,768,853,938,1024};
__constant__ short c_cut1[12]  = {0,86,171,256,342,427,512,598,683,768,854,939};
__constant__ short c_single[8] = {85,170,341,426,597,682,853,938};   // aMin(h), h=1,2,4,5,7,8,10,11
__constant__ signed char c_r1slot[13] = {-1,0,1,-1,2,3,-1,4,5,-1,6,7,-1};

__device__ __forceinline__ float4 f4add(float4 a, float4 b)
{ return make_float4(a.x+b.x, a.y+b.y, a.z+b.z, a.w+b.w); }

// ---------------------------------------------------------------------------
// K1: prep.  grid = 64 + 4*SLOTS = 672, block = 192.
//  blocks [0,64):  W-array build (block = d, thread = j4).
//  rest:           range-partial scan, ~7 rows/slot, 2 accumulators,
//                  single-writer stores, no atomics.
// ---------------------------------------------------------------------------
__global__ void __launch_bounds__(192) prep_kernel(
    const float* __restrict__ value, const float* __restrict__ Wv)
{
    const int x = blockIdx.x, tid = threadIdx.x;

    if (x < 64) {
        const int d = x;
        const float4* wr = (const float4*)Wv;
        float4 u[12];
        #pragma unroll
        for (int c = 0; c < 12; c++)
            u[c] = wr[(size_t)(64 * c + d) * 192 + tid];
        float4 U2 = f4add(f4add(u[8], u[9]),  f4add(u[10], u[11]));
        float4 U1 = f4add(f4add(u[4], u[5]),  f4add(u[6],  u[7]));
        float4 U0 = f4add(f4add(u[0], u[1]),  f4add(u[2],  u[3]));
        float4 W8v = U2;
        float4 W4v = f4add(U1, U2);
        float4 W0v = f4add(U0, W4v);
        float4 L4v = U0;
        float4 L8v = f4add(U0, U1);
        float4* W = (float4*)(g_Acc + W_OFF);
        const size_t o = (size_t)d * 192 + tid;
        W[0 * WARR4 + o] = W0v;
        W[1 * WARR4 + o] = W4v;
        W[2 * WARR4 + o] = W8v;
        W[3 * WARR4 + o] = L4v;
        W[4 * WARR4 + o] = L8v;
    } else {
        const int r  = x - 64;
        const int b  = r / SLOTS;
        const int rr = r % SLOTS;
        int lo, hi;
        if (rr < 12 * NSP) {
            const int h = rr / NSP, sp = rr % NSP;
            const int c1 = c_cut1[h];
            const int L  = c_aMin[h + 1] - c1;     // 84 or 85
            lo = c1 + (L * sp) / NSP;
            hi = c1 + (L * (sp + 1)) / NSP;
        } else {
            lo = c_single[rr - 12 * NSP];
            hi = lo + 1;
        }
        const float4* vp = (const float4*)(value + (size_t)b * SEQ * EMB) + tid;
        float4 a0 = make_float4(0.f, 0.f, 0.f, 0.f), a1 = a0;
        int s = lo;
        for (; s + 1 < hi; s += 2) {
            a0 = f4add(a0, vp[(size_t)s * 192]);
            a1 = f4add(a1, vp[(size_t)(s + 1) * 192]);
        }
        if (s < hi) a0 = f4add(a0, vp[(size_t)s * 192]);
        ((float4*)g_Acc)[(size_t)(b * SLOTS + rr) * 192 + tid] = f4add(a0, a1);
    }
}

// ---------------------------------------------------------------------------
// K2: contract + broadcast (fused, wide).  grid = 384 = (b*12+h)*8 + de,
// 256 threads.  Each block owns an 8-wide d slice (d = de*8 + warp).
//   h%3=0: G = W0*R2 + L4*R3
//   h%3=1: G = W4*R1 + W0*R2 + L8*R3
//   h%3=2: G = W8*R1 + W0*R2
// Each warp computes one d (dot over 768 j), then the block broadcasts its
// 8-float slice to out[b, q, h*64+de*8 ..+8) for all 1024 q.
// ---------------------------------------------------------------------------
__global__ void __launch_bounds__(256) contract_kernel(float* __restrict__ out)
{
    const int x   = blockIdx.x;
    const int b   = x / 96;
    const int rem = x % 96;
    const int h   = rem >> 3;
    const int de  = rem & 7;
    const int tid = threadIdx.x;

    __shared__ float4 R1s[192], R2s[192], R3s[192];
    __shared__ float  Gs[8];

    if (tid < 192) {
        const float4* Pp = (const float4*)g_Acc + (size_t)b * SLOTS * 192;
        float4 a = make_float4(0.f, 0.f, 0.f, 0.f);
        #pragma unroll
        for (int sp = 0; sp < NSP; sp++)
            a = f4add(a, Pp[(size_t)(h * NSP + sp) * 192 + tid]);
        R2s[tid] = a;
        const int s1 = c_r1slot[h];
        R1s[tid] = (s1 >= 0) ? Pp[(size_t)(12 * NSP + s1) * 192 + tid]
                             : make_float4(0.f, 0.f, 0.f, 0.f);
        const int s3 = c_r1slot[h + 1];
        R3s[tid] = (s3 >= 0) ? Pp[(size_t)(12 * NSP + s3) * 192 + tid]
                             : make_float4(0.f, 0.f, 0.f, 0.f);
    }
    __syncthreads();

    const int hm = h % 3;
    const float4* Wbase = (const float4*)(g_Acc + W_OFF);
    const float4* WA = Wbase + (hm == 1 ? 1 : hm == 2 ? 2 : 0) * WARR4;  // R1 coeff
    const float4* WB = Wbase;                                            // W0
    const float4* WC = Wbase + (hm == 0 ? 3 : hm == 1 ? 4 : 0) * WARR4;  // R3 coeff

    const int w = tid >> 5, l = tid & 31;
    {
        const int d = de * 8 + w;
        float s = 0.f;
        #pragma unroll
        for (int i = 0; i < 6; i++) {
            const int idx = l + i * 32;
            float4 a4 = WA[(size_t)d * 192 + idx];
            float4 b4 = WB[(size_t)d * 192 + idx];
            float4 c4 = WC[(size_t)d * 192 + idx];
            float4 r1 = R1s[idx], r2 = R2s[idx], r3 = R3s[idx];
            s += a4.x*r1.x + a4.y*r1.y + a4.z*r1.z + a4.w*r1.w
               + b4.x*r2.x + b4.y*r2.y + b4.z*r2.z + b4.w*r2.w
               + c4.x*r3.x + c4.y*r3.y + c4.z*r3.z + c4.w*r3.w;
        }
        #pragma unroll
        for (int o = 16; o; o >>= 1) s += __shfl_down_sync(~0u, s, o);
        if (l == 0) Gs[w] = s;
    }
    __syncthreads();

    // broadcast: out[b, q, h*64 + de*8 + 0..8) = Gs for all q.
    // 8 floats = 2 float4; tid&1 = col, tid>>1 = row lane (0..127), 8 iters.
    const float4 g0 = ((const float4*)Gs)[tid & 1];
    float* obase = out + (size_t)b * SEQ * EMB + h * HDIM + de * 8;
    const int r0 = tid >> 1;                   // 0..127
    #pragma unroll
    for (int it = 0; it < 8; it++) {
        const int row = it * 128 + r0;
        ((float4*)(obase + (size_t)row * EMB))[tid & 1] = g0;
    }
}

// ---------------------------------------------------------------------------
extern "C" void kernel_launch(void* const* d_in, const int* in_sizes, int n_in,
                              void* d_out, int out_size)
{
    // metadata order: key, query, value, Wk, Wq, Wv
    const float* value = (const float*)d_in[2];
    const float* Wv    = (const float*)d_in[5];
    float* out = (float*)d_out;

    prep_kernel<<<64 + BATCH * SLOTS, 192>>>(value, Wv);
    contract_kernel<<<384, 256>>>(out);
}